// round 17
// baseline (speedup 1.0000x reference)
#include <cuda_runtime.h>
#include <cuda_fp16.h>
#include <cstdint>

#define TSEQ 2048
#define NB   4
#define NH   8
#define HIDD 1024
#define MROWS (NB*TSEQ)   // 8192

#define XF4 2097152
#define WF4 1310720

// ---------------- scratch (device globals; no allocations allowed) ----------
__device__ float g_P [MROWS*4096];
__device__ float g_Bt[MROWS*8];
__device__ float g_O [MROWS*1024];

__device__ __half g_Xh[MROWS*1024];
__device__ __half g_Oh[MROWS*1024];
#define WOFF_O 4194304
__device__ __half g_Wh[5242880];

// ---------------- PTX helpers (sm_80-class only; compute_103-safe) ----------
static __device__ __forceinline__ uint32_t smem_u32(const void* p) {
    uint32_t a;
    asm("{ .reg .u64 t; cvta.to.shared.u64 t, %1; cvt.u32.u64 %0, t; }"
        : "=r"(a) : "l"(p));
    return a;
}

#define LDSM4(r, a)                                                             \
    asm volatile("ldmatrix.sync.aligned.m8n8.x4.shared.b16 {%0,%1,%2,%3}, [%4];"\
        : "=r"((r)[0]), "=r"((r)[1]), "=r"((r)[2]), "=r"((r)[3]) : "r"(a))

#define MMA16816(d, a, b0, b1)                                                  \
    asm volatile(                                                               \
        "mma.sync.aligned.m16n8k16.row.col.f32.f16.f16.f32 "                    \
        "{%0,%1,%2,%3},{%4,%5,%6,%7},{%8,%9},{%0,%1,%2,%3};"                    \
        : "+f"((d)[0]), "+f"((d)[1]), "+f"((d)[2]), "+f"((d)[3])                \
        : "r"((a)[0]), "r"((a)[1]), "r"((a)[2]), "r"((a)[3]), "r"(b0), "r"(b1))

#define CPA16(dst, src)                                                         \
    asm volatile("cp.async.cg.shared.global [%0], [%1], 16;"                    \
        :: "r"(dst), "l"(src) : "memory")
#define CPA4(dst, src)                                                          \
    asm volatile("cp.async.ca.shared.global [%0], [%1], 4;"                     \
        :: "r"(dst), "l"(src) : "memory")

// ---------------- prep: x -> fp16 and all 6 weights -> fp16 (one launch) ----
__global__ __launch_bounds__(256) void prep_fp16(
    const float* __restrict__ x,
    const float* __restrict__ Wq, const float* __restrict__ Wk,
    const float* __restrict__ Wv, const float* __restrict__ Wa,
    const float* __restrict__ Wg, const float* __restrict__ Wo,
    __half* __restrict__ Xh, __half* __restrict__ Wh)
{
    const int i = blockIdx.x * 256 + threadIdx.x;
    if (i < XF4) {
        const float4 v = ((const float4*)x)[i];
        __half2 H0; H0.x = __float2half_rn(v.x); H0.y = __float2half_rn(v.y);
        __half2 H1; H1.x = __float2half_rn(v.z); H1.y = __float2half_rn(v.w);
        *(__half2*)(Xh + (size_t)i * 4)     = H0;
        *(__half2*)(Xh + (size_t)i * 4 + 2) = H1;
        return;
    }
    const int j = i - XF4;
    if (j >= WF4) return;
    const float* src; int base;
    if (j < 262144)      { if (j < 131072) { src = Wq; base = 0; }
                           else            { src = Wk; base = 131072; } }
    else if (j < 786432) { if (j < 524288) { src = Wv; base = 262144; }
                           else            { src = Wa; base = 524288; } }
    else                 { if (j < 1048576){ src = Wg; base = 786432; }
                           else            { src = Wo; base = 1048576; } }
    const float4 v = ((const float4*)src)[j - base];
    __half2 H0; H0.x = __float2half_rn(v.x); H0.y = __float2half_rn(v.y);
    __half2 H1; H1.x = __float2half_rn(v.z); H1.y = __float2half_rn(v.w);
    *(__half2*)(Wh + (size_t)j * 4)     = H0;
    *(__half2*)(Wh + (size_t)j * 4 + 2) = H1;
}

// ------- HMMA GEMM: C = A @ B^T, fp16 inputs, fp32 accum (R16, BK=64) ------
#define STGB  36864u
#define GSMEM (2*36864)

__global__ __launch_bounds__(256, 2) void gemm_hmma(
    const __half* __restrict__ Ah, const __half* __restrict__ Bh,
    const float* __restrict__ bias, float* __restrict__ C, int Nt,
    int bias_lo, int bias_hi, int act_lo)
{
    extern __shared__ char smc[];
    const uint32_t sb = smem_u32(smc);
    const int tid = threadIdx.x;
    const int l   = tid & 31, wid = tid >> 5;
    const int wm  = wid & 1, wn = wid >> 1;
    const int m0  = blockIdx.y << 7, n0 = blockIdx.x << 7;
    const int grp = l >> 3;

    const bool act  = (n0 >= act_lo);
    const bool hasb = bias && (n0 >= bias_lo) && (n0 < bias_hi);

    const uint32_t a_off = (uint32_t)((wm*64 + (grp & 1)*8 + (l & 7)) * 144
                                      + (grp >> 1) * 16);
    const uint32_t b_off = (uint32_t)((wn*32 + (grp >> 1)*8 + (l & 7)) * 144
                                      + (grp & 1) * 16);

    const __half* s0 = Ah + (size_t)m0 * 1024;
    const __half* s1 = Bh + (size_t)n0 * 1024;

    float acc[4][4][4];
#pragma unroll
    for (int mt = 0; mt < 4; mt++)
#pragma unroll
        for (int nt = 0; nt < 4; nt++)
#pragma unroll
            for (int r = 0; r < 4; r++) acc[mt][nt][r] = 0.f;

#define LOAD_BUF(buf, k0) do {                                                  \
    const uint32_t bb_ = sb + (uint32_t)(buf) * STGB;                           \
    const __half* ss_[2] = { s0, s1 };                                          \
    _Pragma("unroll")                                                           \
    for (int t2 = 0; t2 < 2; t2++) {                                            \
        _Pragma("unroll")                                                       \
        for (int it = 0; it < 4; it++) {                                        \
            const int idx_ = it * 256 + tid;                                    \
            const int row_ = idx_ >> 3, ch_ = idx_ & 7;                         \
            const uint32_t dst_ = bb_ + t2 * 18432u + row_ * 144u + ch_ * 16u;  \
            const __half* src_ = ss_[t2] + (size_t)row_ * 1024 + (k0) + ch_ * 8;\
            CPA16(dst_, src_);                                                  \
        }                                                                       \
    }                                                                           \
    asm volatile("cp.async.commit_group;" ::: "memory");                        \
} while (0)

#define MMAPASS(af, bf) do {                                                    \
    _Pragma("unroll")                                                           \
    for (int mt = 0; mt < 4; mt++)                                              \
        _Pragma("unroll")                                                       \
        for (int nt = 0; nt < 4; nt++)                                          \
            MMA16816(acc[mt][nt], (af) + 4*mt,                                  \
                     (bf)[(nt >> 1)*4 + (nt & 1)*2],                            \
                     (bf)[(nt >> 1)*4 + (nt & 1)*2 + 1]);                       \
} while (0)

#define LDSM_SET(av, bv, ko) do {                                               \
    _Pragma("unroll")                                                           \
    for (int np = 0; np < 2; np++)                                              \
        LDSM4((bv) + 4*np, bb + 18432u + b_off + np * 2304u + (ko));            \
    _Pragma("unroll")                                                           \
    for (int mt = 0; mt < 4; mt++)                                              \
        LDSM4((av) + 4*mt, bb + a_off + mt * 2304u + (ko));                     \
} while (0)

    LOAD_BUF(0, 0);

    for (int c = 0; c < 16; c++) {
        asm volatile("cp.async.wait_group 0;" ::: "memory");
        __syncthreads();
        const uint32_t bb = sb + (uint32_t)(c & 1) * STGB;

        uint32_t a0[16], a1[16], b0[8], b1[8];
        LDSM_SET(a0, b0, 0u);
        MMAPASS(a0, b0);

        if (c + 1 < 16) LOAD_BUF((c + 1) & 1, (c + 1) * 64);

        LDSM_SET(a1, b1, 32u);
        MMAPASS(a1, b1);
        LDSM_SET(a0, b0, 64u);
        MMAPASS(a0, b0);
        LDSM_SET(a1, b1, 96u);
        MMAPASS(a1, b1);
    }

    const int r0 = l >> 2, c0 = (l & 3) * 2;
#pragma unroll
    for (int mt = 0; mt < 4; mt++) {
        const int row = m0 + wm*64 + mt*16 + r0;
#pragma unroll
        for (int nt = 0; nt < 4; nt++) {
            const int col = n0 + wn*32 + nt*8 + c0;
            float b0v = 0.f, b1v = 0.f;
            if (hasb) { b0v = bias[col - bias_lo]; b1v = bias[col + 1 - bias_lo]; }
            float v00 = acc[mt][nt][0] + b0v;
            float v01 = acc[mt][nt][1] + b1v;
            float v10 = acc[mt][nt][2] + b0v;
            float v11 = acc[mt][nt][3] + b1v;
            if (act) {
                v00 = 1.f / (1.f + __expf(-v00));
                v01 = 1.f / (1.f + __expf(-v01));
                v10 = 1.f / (1.f + __expf(-v10));
                v11 = 1.f / (1.f + __expf(-v11));
            }
            float2 p0; p0.x = v00; p0.y = v01;
            float2 p1; p1.x = v10; p1.y = v11;
            *(float2*)(C + (size_t)row * Nt + col)       = p0;
            *(float2*)(C + (size_t)(row + 8) * Nt + col) = p1;
        }
    }
}

// ---------------- beta = sigmoid(x @ Wb^T + bb), Wb: (8,1024) ---------------
__global__ __launch_bounds__(256) void beta_proj(
    const float* __restrict__ x, const float* __restrict__ Wb,
    const float* __restrict__ bb, float* __restrict__ Bt)
{
    const int m = blockIdx.x;
    const int w = threadIdx.x >> 5;
    const int lane = threadIdx.x & 31;
    const float* xr = x  + (size_t)m * HIDD;
    const float* wr = Wb + (size_t)w * HIDD;
    float s = 0.f;
#pragma unroll
    for (int k = lane * 4; k < HIDD; k += 128) {
        float4 xv = *(const float4*)(xr + k);
        float4 wv = *(const float4*)(wr + k);
        s += xv.x*wv.x + xv.y*wv.y + xv.z*wv.z + xv.w*wv.w;
    }
#pragma unroll
    for (int o = 16; o; o >>= 1) s += __shfl_xor_sync(0xffffffffu, s, o);
    if (lane == 0) Bt[m*8 + w] = 1.f / (1.f + __expf(-(s + bb[w])));
}

// ------ gated delta-rule recurrence with FUSED depthwise conv+silu ----------
// grid (B*H, 8), block 64: 4 threads/column, 16 columns/block.
// Stages RAW P rows (t0-3..t0+15), computes conv+silu into sk/sq/sv in-kernel.
#define DCH  16
#define RAWR 19

__global__ __launch_bounds__(64) void delta_recurrence(
    const float* __restrict__ P, const float* __restrict__ Bt,
    const float* __restrict__ qcw, const float* __restrict__ qcb,
    const float* __restrict__ kcw, const float* __restrict__ kcb,
    const float* __restrict__ vcw, const float* __restrict__ vcb,
    float* __restrict__ O)
{
    const int bh = blockIdx.x;
    const int b = bh >> 3, h = bh & 7;
    const int ygrp = blockIdx.y;
    const int tid = threadIdx.x;
    const int q_  = tid & 3;
    const int col = tid >> 2;                   // 0..15

    __shared__ __align__(16) float rawK[2][RAWR][68];
    __shared__ __align__(16) float rawQ[2][RAWR][68];
    __shared__ __align__(16) float rawV[2][RAWR][16];
    __shared__ __align__(16) float sk[2][DCH][72];
    __shared__ __align__(16) float sq[2][DCH][72];
    __shared__ __align__(16) float sv[2][DCH][16];
    __shared__ __align__(16) float sa[2][DCH][16];
    __shared__ __align__(16) float sbe[2][DCH];

    const uint32_t rkb = smem_u32(rawK);
    const uint32_t rqb = smem_u32(rawQ);
    const uint32_t rvb = smem_u32(rawV);
    const uint32_t sab = smem_u32(sa);
    const uint32_t sbb = smem_u32(sbe);

    // conv weights (register-resident)
    const int kch = h * 64 + tid;               // k & q channel for this thread
    const float kw0 = kcw[kch*4], kw1 = kcw[kch*4+1],
                kw2 = kcw[kch*4+2], kw3 = kcw[kch*4+3], kbv = kcb[kch];
    const float qw0 = qcw[kch*4], qw1 = qcw[kch*4+1],
                qw2 = qcw[kch*4+2], qw3 = qcw[kch*4+3], qbv = qcb[kch];
    const int vch = h * 128 + ygrp * 16 + (tid >> 2);
    const float vw0 = vcw[vch*4], vw1 = vcw[vch*4+1],
                vw2 = vcw[vch*4+2], vw3 = vcw[vch*4+3], vbv = vcb[vch];
    const int vt0 = (tid & 3) * 4;

    float S[16];
#pragma unroll
    for (int i = 0; i < 16; i++) S[i] = 0.f;

    const float* Pq = P + (size_t)b * TSEQ * 4096 + h * 64;
    const float* Pk = P + (size_t)b * TSEQ * 4096 + 512  + h * 64;
    const float* Pv = P + (size_t)b * TSEQ * 4096 + 1024 + h * 128 + ygrp * 16;
    const float* Pa = P + (size_t)b * TSEQ * 4096 + 2048 + h * 128 + ygrp * 16;
    const float* BtP = Bt + (size_t)b * TSEQ * 8 + h;
    float*       ob  = O  + (size_t)b * TSEQ * 1024 + h * 128 + ygrp * 16 + col;

    // zero raw rows 0..2 of buf0 (causal pad for chunk 0)
    {
        float4 z; z.x = z.y = z.z = z.w = 0.f;
        if (tid < 51) { const int r = tid / 17, f = tid % 17;
                        *(float4*)&rawK[0][r][f*4] = z;
                        *(float4*)&rawQ[0][r][f*4] = z; }
        if (tid < 12) *(float4*)&rawV[0][tid >> 2][(tid & 3) * 4] = z;
    }

#define DSTAGE(buf, t0) do {                                                    \
    _Pragma("unroll")                                                           \
    for (int i = 0; i < 5; i++) {                                               \
        const int idx = i * 64 + tid;                                           \
        const int row = idx >> 4, seg = idx & 15;                               \
        if (row < RAWR) {                                                       \
            const int tm = (t0) - 3 + row;                                      \
            if (tm >= 0) {                                                      \
                CPA16(rkb + (uint32_t)(buf)*(RAWR*68*4) + row*272u + seg*16u,   \
                      Pk + (size_t)tm * 4096 + seg * 4);                        \
                CPA16(rqb + (uint32_t)(buf)*(RAWR*68*4) + row*272u + seg*16u,   \
                      Pq + (size_t)tm * 4096 + seg * 4);                        \
            }                                                                   \
        }                                                                       \
    }                                                                           \
    _Pragma("unroll")                                                           \
    for (int i = 0; i < 2; i++) {                                               \
        const int idx = i * 64 + tid;                                           \
        if (idx < RAWR * 4) {                                                   \
            const int row = idx >> 2, seg = idx & 3;                            \
            const int tm = (t0) - 3 + row;                                      \
            if (tm >= 0)                                                        \
                CPA16(rvb + (uint32_t)(buf)*(RAWR*16*4) + row*64u + seg*16u,    \
                      Pv + (size_t)tm * 4096 + seg * 4);                        \
        }                                                                       \
    }                                                                           \
    {                                                                           \
        const int row = tid >> 2, seg = tid & 3;                                \
        CPA16(sab + (uint32_t)(buf)*(DCH*16*4) + row*64u + seg*16u,             \
              Pa + (size_t)((t0) + row) * 4096 + seg * 4);                      \
    }                                                                           \
    if (tid < DCH)                                                              \
        CPA4(sbb + (uint32_t)(buf)*(DCH*4) + tid*4u,                            \
             BtP + (size_t)((t0) + tid) * 8);                                   \
    asm volatile("cp.async.commit_group;" ::: "memory");                        \
} while (0)

    DSTAGE(0, 0);

    const int NCHUNK = TSEQ / DCH;              // 128
    for (int c = 0; c < NCHUNK; c++) {
        if (c + 1 < NCHUNK) {
            DSTAGE((c + 1) & 1, (c + 1) * DCH);
            asm volatile("cp.async.wait_group 1;" ::: "memory");
        } else {
            asm volatile("cp.async.wait_group 0;" ::: "memory");
        }
        __syncthreads();
        const int buf = c & 1;

        // ---- conv + silu into sk/sq/sv (rolling window; off critical path) --
        {
            const float* rK = &rawK[buf][0][0];
            float x0 = rK[tid], x1 = rK[68 + tid], x2 = rK[136 + tid];
#pragma unroll
            for (int t = 0; t < DCH; t++) {
                const float x3 = rK[(t + 3) * 68 + tid];
                float a = kbv;
                a = fmaf(kw0, x0, a); a = fmaf(kw1, x1, a);
                a = fmaf(kw2, x2, a); a = fmaf(kw3, x3, a);
                sk[buf][t][tid] = a * (1.f / (1.f + __expf(-a))) * 0.125f;
                x0 = x1; x1 = x2; x2 = x3;
            }
            const float* rQ = &rawQ[buf][0][0];
            float y0 = rQ[tid], y1 = rQ[68 + tid], y2 = rQ[136 + tid];
#pragma unroll
            for (int t = 0; t < DCH; t++) {
                const float y3 = rQ[(t + 3) * 68 + tid];
                float a = qbv;
                a = fmaf(qw0, y0, a); a = fmaf(qw1, y1, a);
                a = fmaf(qw2, y2, a); a = fmaf(qw3, y3, a);
                sq[buf][t][tid] = a * (1.f / (1.f + __expf(-a)));
                y0 = y1; y1 = y2; y2 = y3;
            }
            const float* rV = &rawV[buf][0][0];
            const int vc_ = tid >> 2;
            float z0 = rV[vt0*16 + vc_], z1 = rV[(vt0+1)*16 + vc_],
                  z2 = rV[(vt0+2)*16 + vc_];
#pragma unroll
            for (int i = 0; i < 4; i++) {
                const int t = vt0 + i;
                const float z3 = rV[(t + 3) * 16 + vc_];
                float a = vbv;
                a = fmaf(vw0, z0, a); a = fmaf(vw1, z1, a);
                a = fmaf(vw2, z2, a); a = fmaf(vw3, z3, a);
                sv[buf][t][vc_] = a * (1.f / (1.f + __expf(-a)));
                z0 = z1; z1 = z2; z2 = z3;
            }
        }
        __syncthreads();

        // ---- R11 t-loop (unchanged) ----------------------------------------
#pragma unroll 4
        for (int t = 0; t < DCH; t++) {
            const float2* k2 = (const float2*)&sk[buf][t][0];
            const float2* q2 = (const float2*)&sq[buf][t][0];
            const float be_c = sbe[buf][t];
            const float v_c  = sv[buf][t][col];
            const float a_c  = sa[buf][t][col];

            float kr[16];
#pragma unroll
            for (int jj = 0; jj < 8; jj++) {
                const float2 kv = k2[4*jj + q_];
                kr[2*jj]   = kv.x;
                kr[2*jj+1] = kv.y;
            }
            float d0 = 0.f, d1 = 0.f, d2 = 0.f, d3 = 0.f;
#pragma unroll
            for (int jj = 0; jj < 8; jj += 2) {
                d0 = fmaf(kr[2*jj],   S[2*jj],   d0);
                d1 = fmaf(kr[2*jj+1], S[2*jj+1], d1);
                d2 = fmaf(kr[2*jj+2], S[2*jj+2], d2);
                d3 = fmaf(kr[2*jj+3], S[2*jj+3], d3);
            }
            float rd = (d0 + d1) + (d2 + d3);
            rd += __shfl_xor_sync(0xffffffffu, rd, 1);
            rd += __shfl_xor_sync(0xffffffffu, rd, 2);
            const float ncc = be_c * (v_c - rd);

            float o0 = 0.f, o1 = 0.f;
#pragma unroll
            for (int jj = 0; jj < 8; jj++) {
                const float2 qv = q2[4*jj + q_];
                S[2*jj]   = fmaf(a_c, S[2*jj],   ncc * kr[2*jj]);
                S[2*jj+1] = fmaf(a_c, S[2*jj+1], ncc * kr[2*jj+1]);
                o0 = fmaf(qv.x, S[2*jj],   o0);
                o1 = fmaf(qv.y, S[2*jj+1], o1);
            }
            float oo = o0 + o1;
            oo += __shfl_xor_sync(0xffffffffu, oo, 1);
            oo += __shfl_xor_sync(0xffffffffu, oo, 2);
            if (q_ == 0) ob[(size_t)(c * DCH + t) * 1024] = oo;
        }
        __syncthreads();
    }
}

// -------- LayerNorm over DV + sigmoid-gate multiply + fp16 convert ----------
__global__ __launch_bounds__(256) void ln_gate_fp16(
    const float* __restrict__ O, const float* __restrict__ P,
    const float* __restrict__ lnw, const float* __restrict__ lnb,
    __half* __restrict__ hi)
{
    const int g = blockIdx.x * 8 + (threadIdx.x >> 5);
    const int lane = threadIdx.x & 31;
    const int m = g >> 3, h = g & 7;
    const float* row  = O + (size_t)m * 1024 + h * 128;
    const float* grow = P + (size_t)m * 4096 + 3072 + h * 128;

    float xs[4];
    float sum = 0.f;
#pragma unroll
    for (int i = 0; i < 4; i++) { xs[i] = row[lane + 32*i]; sum += xs[i]; }
#pragma unroll
    for (int o = 16; o; o >>= 1) sum += __shfl_xor_sync(0xffffffffu, sum, o);
    const float mu = sum * (1.f / 128.f);

    float vs = 0.f;
#pragma unroll
    for (int i = 0; i < 4; i++) { const float d = xs[i] - mu; vs = fmaf(d, d, vs); }
#pragma unroll
    for (int o = 16; o; o >>= 1) vs += __shfl_xor_sync(0xffffffffu, vs, o);
    const float rstd = rsqrtf(vs * (1.f / 128.f) + 1e-5f);

#pragma unroll
    for (int i = 0; i < 4; i++) {
        const int c = lane + 32*i;
        const float val = ((xs[i] - mu) * rstd * lnw[c] + lnb[c]) * grow[c];
        hi[(size_t)m * 1024 + h * 128 + c] = __float2half_rn(val);
    }
}

// ---------------- launch ----------------------------------------------------
extern "C" void kernel_launch(void* const* d_in, const int* in_sizes, int n_in,
                              void* d_out, int out_size)
{
    const float* x   = (const float*)d_in[0];
    const float* Wq  = (const float*)d_in[1];
    const float* Wk  = (const float*)d_in[2];
    const float* Wv  = (const float*)d_in[3];
    const float* Wa  = (const float*)d_in[4];
    const float* ba  = (const float*)d_in[5];
    const float* Wb  = (const float*)d_in[6];
    const float* bbv = (const float*)d_in[7];
    const float* Wg  = (const float*)d_in[8];
    const float* Wo  = (const float*)d_in[9];
    const float* qcw = (const float*)d_in[10];
    const float* qcb = (const float*)d_in[11];
    const float* kcw = (const float*)d_in[12];
    const float* kcb = (const float*)d_in[13];
    const float* vcw = (const float*)d_in[14];
    const float* vcb = (const float*)d_in[15];
    const float* lnw = (const float*)d_in[16];
    const float* lnb = (const float*)d_in[17];
    float* outp = (float*)d_out;

    float *P, *Bt, *O;
    __half *Xh, *Oh, *Wh;
    cudaGetSymbolAddress((void**)&P,  g_P);
    cudaGetSymbolAddress((void**)&Bt, g_Bt);
    cudaGetSymbolAddress((void**)&O,  g_O);
    cudaGetSymbolAddress((void**)&Xh, g_Xh);
    cudaGetSymbolAddress((void**)&Oh, g_Oh);
    cudaGetSymbolAddress((void**)&Wh, g_Wh);

    cudaFuncSetAttribute(gemm_hmma, cudaFuncAttributeMaxDynamicSharedMemorySize, GSMEM);

    // 0: prep (x + all weights -> fp16)
    prep_fp16<<<(XF4 + WF4 + 255)/256, 256>>>(
        x, Wq, Wk, Wv, Wa, Wg, Wo, Xh, Wh);

    // 1: ONE fused projection GEMM (Q|K|V|A|G), N=4096, BK=64
    gemm_hmma<<<dim3(32, 64), 256, GSMEM>>>(
        Xh, Wh, ba, P, 4096,
        /*bias_lo=*/2048, /*bias_hi=*/3072, /*act_lo=*/2048);

    // 2: beta projection
    beta_proj<<<MROWS, 256>>>(x, Wb, bbv, Bt);

    // 3: delta recurrence with fused depthwise conv+silu  <-- profiled slot
    delta_recurrence<<<dim3(NB*NH, 8), 64>>>(
        P, Bt, qcw, qcb, kcw, kcb, vcw, vcb, O);

    // 4: LN + gate + fp16 convert; 5: output projection
    ln_gate_fp16<<<MROWS, 256>>>(O, P, lnw, lnb, Oh);
    gemm_hmma<<<dim3(8, 64), 256, GSMEM>>>(
        Oh, Wh + WOFF_O, nullptr, outp, 1024,
        /*bias_lo=*/0, /*bias_hi=*/0, /*act_lo=*/1 << 30);
}